// round 2
// baseline (speedup 1.0000x reference)
#include <cuda_runtime.h>

#define NN 50000
#define NE 800000
#define NG 128
#define NH 4
#define HD 64
#define HC 256      // NH*HD
#define JK 576      // 64 + 256 + 256

// ---------------- scratch (static device globals; no allocation) ----------
__device__ float g_h   [NN*HC];   // GEMM output (per-head features)
__device__ float g_acc [NN*HC];   // atomic accumulator / LP ping
__device__ float g_pre [NN*HC];   // relu(gat)+bias  (LP base/residual)
__device__ float g_h1f [NN*HC];   // h1 after label-prop
__device__ float g_h2f [NN*HC];   // h2 after label-prop
__device__ float g_es  [NN*NH];
__device__ float g_ed  [NN*NH];
__device__ float g_emax[NN*NH];
__device__ float g_den [NN*NH];
__device__ float g_eatt[NE*NH];   // exp(e - max), then alpha
__device__ float g_deg [NN];
__device__ float g_dis [NN];
__device__ float g_norm[NE];
__device__ float g_gsum[NG*JK];
__device__ float g_gcnt[NG];

// ---------------- helpers ------------------------------------------------
__global__ void fill_kernel(float* __restrict__ p, float v, int n) {
    int t = blockIdx.x * blockDim.x + threadIdx.x;
    for (; t < n; t += gridDim.x * blockDim.x) p[t] = v;
}

__device__ __forceinline__ void atomicMaxFloat(float* addr, float val) {
    if (val >= 0.0f) atomicMax((int*)addr, __float_as_int(val));
    else             atomicMin((unsigned int*)addr, __float_as_uint(val));
}

// ---------------- GEMM: C[nrows,256] = A[nrows,K] @ W[K,256] --------------
template <int K>
__global__ void gemm_kernel(const float* __restrict__ A,
                            const float* __restrict__ W,
                            float* __restrict__ C, int nrows) {
    __shared__ float As[16][64];
    __shared__ float Bs[16][64];
    const int col0 = blockIdx.x * 64;
    const int row0 = blockIdx.y * 64;
    const int tx = threadIdx.x % 16;   // output col group
    const int ty = threadIdx.x / 16;   // output row group
    float acc[4][4] = {};

    for (int k0 = 0; k0 < K; k0 += 16) {
        #pragma unroll
        for (int i = threadIdx.x; i < 64 * 16; i += 256) {
            int r = i / 16, kk = i % 16;
            int gr = row0 + r;
            As[kk][r] = (gr < nrows) ? A[(long)gr * K + k0 + kk] : 0.0f;
        }
        #pragma unroll
        for (int i = threadIdx.x; i < 16 * 64; i += 256) {
            int kk = i / 64, c = i % 64;
            Bs[kk][c] = W[(k0 + kk) * 256 + col0 + c];
        }
        __syncthreads();
        #pragma unroll
        for (int kk = 0; kk < 16; kk++) {
            float a[4], b[4];
            #pragma unroll
            for (int i = 0; i < 4; i++) a[i] = As[kk][ty * 4 + i];
            #pragma unroll
            for (int j = 0; j < 4; j++) b[j] = Bs[kk][tx * 4 + j];
            #pragma unroll
            for (int i = 0; i < 4; i++)
                #pragma unroll
                for (int j = 0; j < 4; j++) acc[i][j] += a[i] * b[j];
        }
        __syncthreads();
    }
    #pragma unroll
    for (int i = 0; i < 4; i++) {
        int gr = row0 + ty * 4 + i;
        if (gr < nrows) {
            #pragma unroll
            for (int j = 0; j < 4; j++)
                C[(long)gr * 256 + col0 + tx * 4 + j] = acc[i][j];
        }
    }
}

// ---------------- GAT attention ------------------------------------------
__global__ void attn_scores_kernel(const float* __restrict__ h,
                                   const float* __restrict__ a_s,
                                   const float* __restrict__ a_d,
                                   float* __restrict__ es, float* __restrict__ ed) {
    int t = blockIdx.x * blockDim.x + threadIdx.x;
    if (t >= NN * NH) return;
    int nod = t >> 2, hd = t & 3;
    const float* hp = h + (long)nod * HC + hd * HD;
    const float* ap = a_s + hd * HD;
    const float* bp = a_d + hd * HD;
    float s = 0.f, d = 0.f;
    #pragma unroll
    for (int c = 0; c < HD; c++) { float v = hp[c]; s += v * ap[c]; d += v * bp[c]; }
    es[t] = s; ed[t] = d;
}

__global__ void edge_max_kernel(const int* __restrict__ src, const int* __restrict__ dst,
                                const float* __restrict__ es, const float* __restrict__ ed,
                                float* __restrict__ emax) {
    int t = blockIdx.x * blockDim.x + threadIdx.x;
    if (t >= NE * NH) return;
    int e = t >> 2, hd = t & 3;
    int s = src[e], d = dst[e];
    float v = es[s * NH + hd] + ed[d * NH + hd];
    v = (v >= 0.f) ? v : 0.2f * v;
    atomicMaxFloat(&emax[d * NH + hd], v);
}

__global__ void edge_exp_kernel(const int* __restrict__ src, const int* __restrict__ dst,
                                const float* __restrict__ es, const float* __restrict__ ed,
                                const float* __restrict__ emax,
                                float* __restrict__ eatt, float* __restrict__ den) {
    int t = blockIdx.x * blockDim.x + threadIdx.x;
    if (t >= NE * NH) return;
    int e = t >> 2, hd = t & 3;
    int s = src[e], d = dst[e];
    float v = es[s * NH + hd] + ed[d * NH + hd];
    v = (v >= 0.f) ? v : 0.2f * v;
    float ex = __expf(v - emax[d * NH + hd]);
    eatt[t] = ex;
    atomicAdd(&den[d * NH + hd], ex);
}

// Normalize eatt -> alpha in place (one thread per edge-head).
__global__ void alpha_kernel(const int* __restrict__ dst,
                             const float* __restrict__ den,
                             float* __restrict__ eatt) {
    int t = blockIdx.x * blockDim.x + threadIdx.x;
    if (t >= NE * NH) return;
    int e = t >> 2, hd = t & 3;
    float dn = den[dst[e] * NH + hd];
    dn = (dn > 0.f) ? dn : 1.0f;
    eatt[t] = eatt[t] / dn;
}

__global__ void agg_kernel(const int* __restrict__ src, const int* __restrict__ dst,
                           const float* __restrict__ h,
                           const float* __restrict__ alpha,
                           float* __restrict__ acc) {
    int t = blockIdx.x * blockDim.x + threadIdx.x;   // NE*64 threads (float4 each)
    if (t >= NE * 64) return;
    int e = t >> 6, j = t & 63;        // j: float4 index, head = j/16
    int hd = j >> 4;
    int s = src[e], d = dst[e];
    float a = alpha[e * NH + hd];
    float4 v = *(const float4*)&h[(long)s * HC + j * 4];
    float* out = &acc[(long)d * HC + j * 4];
    atomicAdd(out + 0, v.x * a);
    atomicAdd(out + 1, v.y * a);
    atomicAdd(out + 2, v.z * a);
    atomicAdd(out + 3, v.w * a);
}

__global__ void bias_relu_kernel(const float* __restrict__ acc, const float* __restrict__ b,
                                 float* __restrict__ out) {
    int t = blockIdx.x * blockDim.x + threadIdx.x;   // NN*HC/4 threads
    if (t >= NN * HC / 4) return;
    int col4 = t & (HC / 4 - 1);
    float4 v = ((const float4*)acc)[t];
    float4 bb = ((const float4*)b)[col4];
    v.x = fmaxf(v.x + bb.x, 0.f);
    v.y = fmaxf(v.y + bb.y, 0.f);
    v.z = fmaxf(v.z + bb.z, 0.f);
    v.w = fmaxf(v.w + bb.w, 0.f);
    ((float4*)out)[t] = v;
}

// ---------------- Label propagation --------------------------------------
__global__ void deg_kernel(const int* __restrict__ dst, float* __restrict__ deg) {
    int e = blockIdx.x * blockDim.x + threadIdx.x;
    if (e >= NE) return;
    atomicAdd(&deg[dst[e]], 1.0f);
}

__global__ void dis_kernel(const float* __restrict__ deg, float* __restrict__ dis) {
    int t = blockIdx.x * blockDim.x + threadIdx.x;
    if (t >= NN) return;
    float dg = deg[t];
    dis[t] = (dg > 0.f) ? rsqrtf(fmaxf(dg, 1.0f)) : 0.0f;
}

__global__ void norm_kernel(const int* __restrict__ src, const int* __restrict__ dst,
                            const float* __restrict__ dis, float* __restrict__ nrm) {
    int e = blockIdx.x * blockDim.x + threadIdx.x;
    if (e >= NE) return;
    nrm[e] = dis[src[e]] * dis[dst[e]];
}

__global__ void lp_scatter_kernel(const int* __restrict__ src, const int* __restrict__ dst,
                                  const float* __restrict__ in, const float* __restrict__ nrm,
                                  float* __restrict__ acc) {
    int t = blockIdx.x * blockDim.x + threadIdx.x;   // NE*64
    if (t >= NE * 64) return;
    int e = t >> 6, j = t & 63;
    int s = src[e], d = dst[e];
    float w = nrm[e];
    float4 v = *(const float4*)&in[(long)s * HC + j * 4];
    float* out = &acc[(long)d * HC + j * 4];
    atomicAdd(out + 0, v.x * w);
    atomicAdd(out + 1, v.y * w);
    atomicAdd(out + 2, v.z * w);
    atomicAdd(out + 3, v.w * w);
}

__global__ void lp_update_kernel(const float* __restrict__ acc, const float* __restrict__ base,
                                 float* __restrict__ out) {
    int t = blockIdx.x * blockDim.x + threadIdx.x;   // NN*HC/4
    if (t >= NN * HC / 4) return;
    float4 a = ((const float4*)acc)[t];
    float4 b = ((const float4*)base)[t];
    float4 o;
    o.x = fminf(fmaxf(0.5f * a.x + 0.5f * b.x, 0.f), 1.f);
    o.y = fminf(fmaxf(0.5f * a.y + 0.5f * b.y, 0.f), 1.f);
    o.z = fminf(fmaxf(0.5f * a.z + 0.5f * b.z, 0.f), 1.f);
    o.w = fminf(fmaxf(0.5f * a.w + 0.5f * b.w, 0.f), 1.f);
    ((float4*)out)[t] = o;
}

// ---------------- Pooling -------------------------------------------------
__global__ void count_kernel(const int* __restrict__ batch, float* __restrict__ cnt) {
    int t = blockIdx.x * blockDim.x + threadIdx.x;
    if (t >= NN) return;
    atomicAdd(&cnt[batch[t]], 1.0f);
}

__global__ void pool_kernel(const float* __restrict__ x,
                            const float* __restrict__ h1, const float* __restrict__ h2,
                            const int* __restrict__ batch, float* __restrict__ gsum) {
    int t = blockIdx.x * blockDim.x + threadIdx.x;   // NN * 144 (float4 per 576)
    if (t >= NN * 144) return;
    int n = t / 144, c4 = t % 144;
    int col = c4 * 4;
    float4 v;
    if (col < 64)       v = *(const float4*)&x [(long)n * 64 + col];
    else if (col < 320) v = *(const float4*)&h1[(long)n * HC + (col - 64)];
    else                v = *(const float4*)&h2[(long)n * HC + (col - 320)];
    float* out = &gsum[batch[n] * JK + col];
    atomicAdd(out + 0, v.x);
    atomicAdd(out + 1, v.y);
    atomicAdd(out + 2, v.z);
    atomicAdd(out + 3, v.w);
}

// ---------------- Head MLPs (one block per graph) -------------------------
__global__ void head_kernel(const float* __restrict__ gsum, const float* __restrict__ gcnt,
                            const float* __restrict__ clin,
                            const float* __restrict__ pp_w1, const float* __restrict__ pp_b1,
                            const float* __restrict__ pp_w2, const float* __restrict__ pp_b2,
                            const float* __restrict__ cl_w1, const float* __restrict__ cl_b1,
                            const float* __restrict__ cl_w2, const float* __restrict__ cl_b2,
                            const float* __restrict__ h_w1, const float* __restrict__ h_b1,
                            const float* __restrict__ h_w2, const float* __restrict__ h_b2,
                            const float* __restrict__ h_w3, const float* __restrict__ h_b3,
                            float* __restrict__ out) {
    __shared__ float g[JK];
    __shared__ float t1[256];
    __shared__ float z[160];
    __shared__ float c1s[64];
    __shared__ float t3[64];
    __shared__ float t4[32];
    int b = blockIdx.x, tid = threadIdx.x;
    float cnt = fmaxf(gcnt[b], 1.0f);
    for (int i = tid; i < JK; i += 256) g[i] = gsum[b * JK + i] / cnt;
    __syncthreads();

    // pp layer1: 576 -> 256 (relu)
    {
        float o = pp_b1[tid];
        for (int k = 0; k < JK; k++) o += g[k] * pp_w1[k * 256 + tid];
        t1[tid] = o > 0.f ? o : 0.f;
    }
    __syncthreads();
    // pp layer2: 256 -> 128
    if (tid < 128) {
        float o = pp_b2[tid];
        for (int k = 0; k < 256; k++) o += t1[k] * pp_w2[k * 128 + tid];
        z[tid] = o;
    }
    // clinical layer1: 32 -> 64 (relu)
    if (tid >= 128 && tid < 192) {
        int c = tid - 128;
        float o = cl_b1[c];
        for (int k = 0; k < 32; k++) o += clin[b * 32 + k] * cl_w1[k * 64 + c];
        c1s[c] = o > 0.f ? o : 0.f;
    }
    __syncthreads();
    // clinical layer2: 64 -> 32
    if (tid < 32) {
        float o = cl_b2[tid];
        for (int k = 0; k < 64; k++) o += c1s[k] * cl_w2[k * 32 + tid];
        z[128 + tid] = o;
    }
    __syncthreads();
    // head 1: 160 -> 64 (relu)
    if (tid < 64) {
        float o = h_b1[tid];
        for (int k = 0; k < 160; k++) o += z[k] * h_w1[k * 64 + tid];
        t3[tid] = o > 0.f ? o : 0.f;
    }
    __syncthreads();
    // head 2: 64 -> 32 (relu)
    if (tid < 32) {
        float o = h_b2[tid];
        for (int k = 0; k < 64; k++) o += t3[k] * h_w2[k * 32 + tid];
        t4[tid] = o > 0.f ? o : 0.f;
    }
    __syncthreads();
    // head 3: 32 -> 2
    if (tid < 2) {
        float o = h_b3[tid];
        for (int k = 0; k < 32; k++) o += t4[k] * h_w3[k * 2 + tid];
        out[b * 2 + tid] = o;
    }
}

// ---------------- launch --------------------------------------------------
static inline int cdiv(long a, int b) { return (int)((a + b - 1) / b); }

extern "C" void kernel_launch(void* const* d_in, const int* in_sizes, int n_in,
                              void* d_out, int out_size) {
    const float* x     = (const float*)d_in[0];
    const int*   ei    = (const int*)  d_in[1];
    const int*   batch = (const int*)  d_in[2];
    const float* clin  = (const float*)d_in[3];
    const float* W1  = (const float*)d_in[4];
    const float* a1s = (const float*)d_in[5];
    const float* a1d = (const float*)d_in[6];
    const float* b1  = (const float*)d_in[7];
    const float* W2  = (const float*)d_in[8];
    const float* a2s = (const float*)d_in[9];
    const float* a2d = (const float*)d_in[10];
    const float* b2  = (const float*)d_in[11];
    const float* pp_w1 = (const float*)d_in[12];
    const float* pp_b1 = (const float*)d_in[13];
    const float* pp_w2 = (const float*)d_in[14];
    const float* pp_b2 = (const float*)d_in[15];
    const float* cl_w1 = (const float*)d_in[16];
    const float* cl_b1 = (const float*)d_in[17];
    const float* cl_w2 = (const float*)d_in[18];
    const float* cl_b2 = (const float*)d_in[19];
    const float* h_w1 = (const float*)d_in[20];
    const float* h_b1 = (const float*)d_in[21];
    const float* h_w2 = (const float*)d_in[22];
    const float* h_b2 = (const float*)d_in[23];
    const float* h_w3 = (const float*)d_in[24];
    const float* h_b3 = (const float*)d_in[25];
    float* out = (float*)d_out;

    const int* src = ei;
    const int* dst = ei + NE;

    float *p_h, *p_acc, *p_pre, *p_h1f, *p_h2f;
    float *p_es, *p_ed, *p_emax, *p_den, *p_eatt, *p_deg, *p_dis, *p_norm, *p_gsum, *p_gcnt;
    cudaGetSymbolAddress((void**)&p_h,    g_h);
    cudaGetSymbolAddress((void**)&p_acc,  g_acc);
    cudaGetSymbolAddress((void**)&p_pre,  g_pre);
    cudaGetSymbolAddress((void**)&p_h1f,  g_h1f);
    cudaGetSymbolAddress((void**)&p_h2f,  g_h2f);
    cudaGetSymbolAddress((void**)&p_es,   g_es);
    cudaGetSymbolAddress((void**)&p_ed,   g_ed);
    cudaGetSymbolAddress((void**)&p_emax, g_emax);
    cudaGetSymbolAddress((void**)&p_den,  g_den);
    cudaGetSymbolAddress((void**)&p_eatt, g_eatt);
    cudaGetSymbolAddress((void**)&p_deg,  g_deg);
    cudaGetSymbolAddress((void**)&p_dis,  g_dis);
    cudaGetSymbolAddress((void**)&p_norm, g_norm);
    cudaGetSymbolAddress((void**)&p_gsum, g_gsum);
    cudaGetSymbolAddress((void**)&p_gcnt, g_gcnt);

    const int TB = 256;
    dim3 ggrid(4, cdiv(NN, 64));

    // ---- degree / norm (shared by both LP calls) ----
    fill_kernel<<<256, TB>>>(p_deg, 0.0f, NN);
    deg_kernel<<<cdiv(NE, TB), TB>>>(dst, p_deg);
    dis_kernel<<<cdiv(NN, TB), TB>>>(p_deg, p_dis);
    norm_kernel<<<cdiv(NE, TB), TB>>>(src, dst, p_dis, p_norm);

    for (int layer = 0; layer < 2; layer++) {
        const float* a_s = layer ? a2s : a1s;
        const float* a_d = layer ? a2d : a1d;
        const float* bb  = layer ? b2  : b1;
        float* outbuf    = layer ? p_h2f : p_h1f;

        // GEMM
        if (layer == 0) gemm_kernel<64><<<ggrid, TB>>>(x, W1, p_h, NN);
        else            gemm_kernel<256><<<ggrid, TB>>>(p_h1f, W2, p_h, NN);

        // attention
        attn_scores_kernel<<<cdiv((long)NN * NH, TB), TB>>>(p_h, a_s, a_d, p_es, p_ed);
        fill_kernel<<<256, TB>>>(p_emax, -1e30f, NN * NH);
        fill_kernel<<<256, TB>>>(p_den, 0.0f, NN * NH);
        fill_kernel<<<2048, TB>>>(p_acc, 0.0f, NN * HC);
        edge_max_kernel<<<cdiv((long)NE * NH, TB), TB>>>(src, dst, p_es, p_ed, p_emax);
        edge_exp_kernel<<<cdiv((long)NE * NH, TB), TB>>>(src, dst, p_es, p_ed, p_emax, p_eatt, p_den);
        alpha_kernel<<<cdiv((long)NE * NH, TB), TB>>>(dst, p_den, p_eatt);
        agg_kernel<<<cdiv((long)NE * 64, TB), TB>>>(src, dst, p_h, p_eatt, p_acc);
        bias_relu_kernel<<<cdiv((long)NN * HC / 4, TB), TB>>>(p_acc, bb, p_pre);

        // label prop (2 iters); use p_h as scatter scratch, p_acc as ping
        fill_kernel<<<2048, TB>>>(p_h, 0.0f, NN * HC);
        lp_scatter_kernel<<<cdiv((long)NE * 64, TB), TB>>>(src, dst, p_pre, p_norm, p_h);
        lp_update_kernel<<<cdiv((long)NN * HC / 4, TB), TB>>>(p_h, p_pre, p_acc);
        fill_kernel<<<2048, TB>>>(p_h, 0.0f, NN * HC);
        lp_scatter_kernel<<<cdiv((long)NE * 64, TB), TB>>>(src, dst, p_acc, p_norm, p_h);
        lp_update_kernel<<<cdiv((long)NN * HC / 4, TB), TB>>>(p_h, p_pre, outbuf);
    }

    // ================= pooling + heads =================
    fill_kernel<<<128, TB>>>(p_gsum, 0.0f, NG * JK);
    fill_kernel<<<1, TB>>>(p_gcnt, 0.0f, NG);
    count_kernel<<<cdiv(NN, TB), TB>>>(batch, p_gcnt);
    pool_kernel<<<cdiv((long)NN * 144, TB), TB>>>(x, p_h1f, p_h2f, batch, p_gsum);
    head_kernel<<<NG, TB>>>(p_gsum, p_gcnt, clin,
                            pp_w1, pp_b1, pp_w2, pp_b2,
                            cl_w1, cl_b1, cl_w2, cl_b2,
                            h_w1, h_b1, h_w2, h_b2, h_w3, h_b3,
                            out);
}

// round 4
// speedup vs baseline: 3.4336x; 3.4336x over previous
#include <cuda_runtime.h>

#define NN 50000
#define NE 800000
#define NG 128
#define NH 4
#define HD 64
#define HC 256      // NH*HD
#define JK 576      // 64 + 256 + 256

// ---------------- scratch (static device globals; no allocation) ----------
__device__ float g_h   [NN*HC];   // GEMM output (per-head features)
__device__ float g_acc [NN*HC];   // LP ping buffer
__device__ float g_pre [NN*HC];   // relu(gat)+bias  (LP base/residual)
__device__ float g_h1f [NN*HC];   // h1 after label-prop
__device__ float g_h2f [NN*HC];   // h2 after label-prop
__device__ float g_es  [NN*NH];
__device__ float g_ed  [NN*NH];
__device__ float g_alpha[NE*NH];  // CSR-position-ordered attention weights
__device__ float g_dis [NN];
__device__ int   g_cnt [NN];
__device__ int   g_pos [NN];
__device__ int   g_rowptr[NN+1];
__device__ int   g_srcs[NE];      // CSR-ordered source node ids
__device__ float g_gmean[NG*JK];

// ---------------- CSR construction ----------------------------------------
__global__ void ifill_kernel(int* __restrict__ p, int v, int n) {
    int t = blockIdx.x * blockDim.x + threadIdx.x;
    for (; t < n; t += gridDim.x * blockDim.x) p[t] = v;
}

__global__ void count_deg_kernel(const int* __restrict__ dst, int* __restrict__ cnt) {
    int e = blockIdx.x * blockDim.x + threadIdx.x;
    if (e >= NE) return;
    atomicAdd(&cnt[dst[e]], 1);
}

__global__ void scan_kernel(const int* __restrict__ cnt, int* __restrict__ rowptr,
                            int* __restrict__ pos) {
    __shared__ int part[1024];
    int tid = threadIdx.x;
    const int CH = (NN + 1023) / 1024;
    int start = tid * CH;
    int end = start + CH < NN ? start + CH : NN;
    int s = 0;
    for (int i = start; i < end; i++) s += cnt[i];
    part[tid] = s;
    __syncthreads();
    for (int off = 1; off < 1024; off <<= 1) {
        int u = (tid >= off) ? part[tid - off] : 0;
        __syncthreads();
        part[tid] += u;
        __syncthreads();
    }
    int base = (tid > 0) ? part[tid - 1] : 0;
    for (int i = start; i < end; i++) {
        rowptr[i] = base;
        pos[i] = base;
        base += cnt[i];
    }
    if (tid == 1023) rowptr[NN] = part[1023];
}

// Write CSR-ordered source ids directly (no eperm indirection downstream).
__global__ void perm_kernel(const int* __restrict__ src, const int* __restrict__ dst,
                            int* __restrict__ pos, int* __restrict__ srcs) {
    int e = blockIdx.x * blockDim.x + threadIdx.x;
    if (e >= NE) return;
    int p = atomicAdd(&pos[dst[e]], 1);
    srcs[p] = src[e];
}

__global__ void dis_kernel(const int* __restrict__ rowptr, float* __restrict__ dis) {
    int t = blockIdx.x * blockDim.x + threadIdx.x;
    if (t >= NN) return;
    int dg = rowptr[t + 1] - rowptr[t];
    dis[t] = (dg > 0) ? rsqrtf((float)dg) : 0.0f;
}

// ---------------- GEMM: C[nrows,256] = A[nrows,K] @ W[K,256] --------------
template <int K>
__global__ void gemm_kernel(const float* __restrict__ A,
                            const float* __restrict__ W,
                            float* __restrict__ C, int nrows) {
    __shared__ float As[16][64];
    __shared__ float Bs[16][64];
    const int col0 = blockIdx.x * 64;
    const int row0 = blockIdx.y * 64;
    const int tx = threadIdx.x % 16;
    const int ty = threadIdx.x / 16;
    float acc[4][4] = {};

    for (int k0 = 0; k0 < K; k0 += 16) {
        #pragma unroll
        for (int i = threadIdx.x; i < 64 * 16; i += 256) {
            int r = i / 16, kk = i % 16;
            int gr = row0 + r;
            As[kk][r] = (gr < nrows) ? A[(long)gr * K + k0 + kk] : 0.0f;
        }
        #pragma unroll
        for (int i = threadIdx.x; i < 16 * 64; i += 256) {
            int kk = i / 64, c = i % 64;
            Bs[kk][c] = W[(k0 + kk) * 256 + col0 + c];
        }
        __syncthreads();
        #pragma unroll
        for (int kk = 0; kk < 16; kk++) {
            float a[4], b[4];
            #pragma unroll
            for (int i = 0; i < 4; i++) a[i] = As[kk][ty * 4 + i];
            #pragma unroll
            for (int j = 0; j < 4; j++) b[j] = Bs[kk][tx * 4 + j];
            #pragma unroll
            for (int i = 0; i < 4; i++)
                #pragma unroll
                for (int j = 0; j < 4; j++) acc[i][j] += a[i] * b[j];
        }
        __syncthreads();
    }
    #pragma unroll
    for (int i = 0; i < 4; i++) {
        int gr = row0 + ty * 4 + i;
        if (gr < nrows) {
            #pragma unroll
            for (int j = 0; j < 4; j++)
                C[(long)gr * 256 + col0 + tx * 4 + j] = acc[i][j];
        }
    }
}

// ---------------- GAT attention ------------------------------------------
__global__ void attn_scores_kernel(const float* __restrict__ h,
                                   const float* __restrict__ a_s,
                                   const float* __restrict__ a_d,
                                   float* __restrict__ es, float* __restrict__ ed) {
    int t = blockIdx.x * blockDim.x + threadIdx.x;
    if (t >= NN * NH) return;
    int nod = t >> 2, hd = t & 3;
    const float* hp = h + (long)nod * HC + hd * HD;
    const float* ap = a_s + hd * HD;
    const float* bp = a_d + hd * HD;
    float s = 0.f, d = 0.f;
    #pragma unroll
    for (int c = 0; c < HD; c++) { float v = hp[c]; s += v * ap[c]; d += v * bp[c]; }
    es[t] = s; ed[t] = d;
}

// Per-(dst,head) softmax over incoming edges (CSR order, streaming).
__global__ void softmax_kernel(const int* __restrict__ rowptr, const int* __restrict__ srcs,
                               const float* __restrict__ es, const float* __restrict__ ed,
                               float* __restrict__ alpha) {
    int t = blockIdx.x * blockDim.x + threadIdx.x;
    if (t >= NN * NH) return;
    int n = t >> 2, hd = t & 3;
    int b = rowptr[n], e_ = rowptr[n + 1];
    float edn = ed[n * NH + hd];
    float m = -1e30f;
    for (int i = b; i < e_; i++) {
        float v = es[srcs[i] * NH + hd] + edn;
        v = (v >= 0.f) ? v : 0.2f * v;
        m = fmaxf(m, v);
    }
    float den = 0.f;
    for (int i = b; i < e_; i++) {
        float v = es[srcs[i] * NH + hd] + edn;
        v = (v >= 0.f) ? v : 0.2f * v;
        float ex = __expf(v - m);
        alpha[i * NH + hd] = ex;
        den += ex;
    }
    float inv = (den > 0.f) ? 1.0f / den : 1.0f;
    for (int i = b; i < e_; i++) {
        alpha[i * NH + hd] *= inv;
    }
}

// Gather-aggregate + bias + relu fused. One thread per (node, float4 lane).
__global__ void gat_gather_kernel(const int* __restrict__ rowptr, const int* __restrict__ srcs,
                                  const float* __restrict__ h, const float* __restrict__ alpha,
                                  const float* __restrict__ bias, float* __restrict__ out) {
    int t = blockIdx.x * blockDim.x + threadIdx.x;
    if (t >= NN * 64) return;
    int n = t >> 6, j = t & 63;
    int hd = j >> 4;
    int b = rowptr[n], e_ = rowptr[n + 1];
    float4 acc = make_float4(0.f, 0.f, 0.f, 0.f);
    for (int i = b; i < e_; i++) {
        int s = srcs[i];
        float a = alpha[i * NH + hd];
        float4 v = *(const float4*)&h[(long)s * HC + j * 4];
        acc.x += a * v.x; acc.y += a * v.y; acc.z += a * v.z; acc.w += a * v.w;
    }
    float4 bb = ((const float4*)bias)[j];
    acc.x = fmaxf(acc.x + bb.x, 0.f);
    acc.y = fmaxf(acc.y + bb.y, 0.f);
    acc.z = fmaxf(acc.z + bb.z, 0.f);
    acc.w = fmaxf(acc.w + bb.w, 0.f);
    ((float4*)out)[t] = acc;
}

// LP gather + mix + clamp fused. out = clamp(0.5*gather(in) + 0.5*base, 0, 1)
__global__ void lp_gather_kernel(const int* __restrict__ rowptr, const int* __restrict__ srcs,
                                 const float* __restrict__ in, const float* __restrict__ dis,
                                 const float* __restrict__ base, float* __restrict__ out) {
    int t = blockIdx.x * blockDim.x + threadIdx.x;
    if (t >= NN * 64) return;
    int n = t >> 6, j = t & 63;
    int b = rowptr[n], e_ = rowptr[n + 1];
    float dn = dis[n];
    float4 acc = make_float4(0.f, 0.f, 0.f, 0.f);
    for (int i = b; i < e_; i++) {
        int s = srcs[i];
        float w = dis[s];
        float4 v = *(const float4*)&in[(long)s * HC + j * 4];
        acc.x += w * v.x; acc.y += w * v.y; acc.z += w * v.z; acc.w += w * v.w;
    }
    float4 bs = ((const float4*)base)[t];
    float4 o;
    o.x = fminf(fmaxf(0.5f * dn * acc.x + 0.5f * bs.x, 0.f), 1.f);
    o.y = fminf(fmaxf(0.5f * dn * acc.y + 0.5f * bs.y, 0.f), 1.f);
    o.z = fminf(fmaxf(0.5f * dn * acc.z + 0.5f * bs.z, 0.f), 1.f);
    o.w = fminf(fmaxf(0.5f * dn * acc.w + 0.5f * bs.w, 0.f), 1.f);
    ((float4*)out)[t] = o;
}

// ---------------- Pooling (batch is sorted -> contiguous ranges) ----------
__device__ __forceinline__ int lower_bound_batch(const int* __restrict__ batch, int key) {
    int lo = 0, hi = NN;
    while (lo < hi) {
        int mid = (lo + hi) >> 1;
        if (batch[mid] < key) lo = mid + 1; else hi = mid;
    }
    return lo;
}

__global__ void pool_kernel(const float* __restrict__ x,
                            const float* __restrict__ h1, const float* __restrict__ h2,
                            const int* __restrict__ batch, float* __restrict__ gmean) {
    int b = blockIdx.x;          // graph id
    int tid = threadIdx.x;       // 0..575 = column
    __shared__ int s_start, s_end;
    if (tid == 0) {
        s_start = lower_bound_batch(batch, b);
        s_end   = lower_bound_batch(batch, b + 1);
    }
    __syncthreads();
    int start = s_start, end = s_end;
    float s = 0.f;
    if (tid < 64) {
        for (int n = start; n < end; n++) s += x[(long)n * 64 + tid];
    } else if (tid < 320) {
        int c = tid - 64;
        for (int n = start; n < end; n++) s += h1[(long)n * HC + c];
    } else {
        int c = tid - 320;
        for (int n = start; n < end; n++) s += h2[(long)n * HC + c];
    }
    float cnt = (float)(end - start);
    cnt = fmaxf(cnt, 1.0f);
    gmean[b * JK + tid] = s / cnt;
}

// ---------------- Head MLPs (one block per graph) -------------------------
__global__ void head_kernel(const float* __restrict__ gmean,
                            const float* __restrict__ clin,
                            const float* __restrict__ pp_w1, const float* __restrict__ pp_b1,
                            const float* __restrict__ pp_w2, const float* __restrict__ pp_b2,
                            const float* __restrict__ cl_w1, const float* __restrict__ cl_b1,
                            const float* __restrict__ cl_w2, const float* __restrict__ cl_b2,
                            const float* __restrict__ h_w1, const float* __restrict__ h_b1,
                            const float* __restrict__ h_w2, const float* __restrict__ h_b2,
                            const float* __restrict__ h_w3, const float* __restrict__ h_b3,
                            float* __restrict__ out) {
    __shared__ float g[JK];
    __shared__ float t1[256];
    __shared__ float z[160];
    __shared__ float c1s[64];
    __shared__ float t3[64];
    __shared__ float t4[32];
    int b = blockIdx.x, tid = threadIdx.x;
    for (int i = tid; i < JK; i += 256) g[i] = gmean[b * JK + i];
    __syncthreads();

    // pp layer1: 576 -> 256 (relu)
    {
        float o = pp_b1[tid];
        for (int k = 0; k < JK; k++) o += g[k] * pp_w1[k * 256 + tid];
        t1[tid] = o > 0.f ? o : 0.f;
    }
    __syncthreads();
    // pp layer2: 256 -> 128
    if (tid < 128) {
        float o = pp_b2[tid];
        for (int k = 0; k < 256; k++) o += t1[k] * pp_w2[k * 128 + tid];
        z[tid] = o;
    }
    // clinical layer1: 32 -> 64 (relu)
    if (tid >= 128 && tid < 192) {
        int c = tid - 128;
        float o = cl_b1[c];
        for (int k = 0; k < 32; k++) o += clin[b * 32 + k] * cl_w1[k * 64 + c];
        c1s[c] = o > 0.f ? o : 0.f;
    }
    __syncthreads();
    // clinical layer2: 64 -> 32
    if (tid < 32) {
        float o = cl_b2[tid];
        for (int k = 0; k < 64; k++) o += c1s[k] * cl_w2[k * 32 + tid];
        z[128 + tid] = o;
    }
    __syncthreads();
    // head 1: 160 -> 64 (relu)
    if (tid < 64) {
        float o = h_b1[tid];
        for (int k = 0; k < 160; k++) o += z[k] * h_w1[k * 64 + tid];
        t3[tid] = o > 0.f ? o : 0.f;
    }
    __syncthreads();
    // head 2: 64 -> 32 (relu)
    if (tid < 32) {
        float o = h_b2[tid];
        for (int k = 0; k < 64; k++) o += t3[k] * h_w2[k * 32 + tid];
        t4[tid] = o > 0.f ? o : 0.f;
    }
    __syncthreads();
    // head 3: 32 -> 2
    if (tid < 2) {
        float o = h_b3[tid];
        for (int k = 0; k < 32; k++) o += t4[k] * h_w3[k * 2 + tid];
        out[b * 2 + tid] = o;
    }
}

// ---------------- launch --------------------------------------------------
static inline int cdiv(long a, int b) { return (int)((a + b - 1) / b); }

extern "C" void kernel_launch(void* const* d_in, const int* in_sizes, int n_in,
                              void* d_out, int out_size) {
    const float* x     = (const float*)d_in[0];
    const int*   ei    = (const int*)  d_in[1];
    const int*   batch = (const int*)  d_in[2];
    const float* clin  = (const float*)d_in[3];
    const float* W1  = (const float*)d_in[4];
    const float* a1s = (const float*)d_in[5];
    const float* a1d = (const float*)d_in[6];
    const float* b1  = (const float*)d_in[7];
    const float* W2  = (const float*)d_in[8];
    const float* a2s = (const float*)d_in[9];
    const float* a2d = (const float*)d_in[10];
    const float* b2  = (const float*)d_in[11];
    const float* pp_w1 = (const float*)d_in[12];
    const float* pp_b1 = (const float*)d_in[13];
    const float* pp_w2 = (const float*)d_in[14];
    const float* pp_b2 = (const float*)d_in[15];
    const float* cl_w1 = (const float*)d_in[16];
    const float* cl_b1 = (const float*)d_in[17];
    const float* cl_w2 = (const float*)d_in[18];
    const float* cl_b2 = (const float*)d_in[19];
    const float* h_w1 = (const float*)d_in[20];
    const float* h_b1 = (const float*)d_in[21];
    const float* h_w2 = (const float*)d_in[22];
    const float* h_b2 = (const float*)d_in[23];
    const float* h_w3 = (const float*)d_in[24];
    const float* h_b3 = (const float*)d_in[25];
    float* out = (float*)d_out;

    const int* src = ei;
    const int* dst = ei + NE;

    float *p_h, *p_acc, *p_pre, *p_h1f, *p_h2f, *p_es, *p_ed, *p_alpha, *p_dis, *p_gmean;
    int *p_cnt, *p_pos, *p_rowptr, *p_srcs;
    cudaGetSymbolAddress((void**)&p_h,     g_h);
    cudaGetSymbolAddress((void**)&p_acc,   g_acc);
    cudaGetSymbolAddress((void**)&p_pre,   g_pre);
    cudaGetSymbolAddress((void**)&p_h1f,   g_h1f);
    cudaGetSymbolAddress((void**)&p_h2f,   g_h2f);
    cudaGetSymbolAddress((void**)&p_es,    g_es);
    cudaGetSymbolAddress((void**)&p_ed,    g_ed);
    cudaGetSymbolAddress((void**)&p_alpha, g_alpha);
    cudaGetSymbolAddress((void**)&p_dis,   g_dis);
    cudaGetSymbolAddress((void**)&p_gmean, g_gmean);
    cudaGetSymbolAddress((void**)&p_cnt,   g_cnt);
    cudaGetSymbolAddress((void**)&p_pos,   g_pos);
    cudaGetSymbolAddress((void**)&p_rowptr,g_rowptr);
    cudaGetSymbolAddress((void**)&p_srcs,  g_srcs);

    const int TB = 256;
    dim3 ggrid(4, cdiv(NN, 64));

    // ---- CSR by dst (shared by softmax, GAT gather, LP gather) ----
    ifill_kernel<<<64, TB>>>(p_cnt, 0, NN);
    count_deg_kernel<<<cdiv(NE, TB), TB>>>(dst, p_cnt);
    scan_kernel<<<1, 1024>>>(p_cnt, p_rowptr, p_pos);
    perm_kernel<<<cdiv(NE, TB), TB>>>(src, dst, p_pos, p_srcs);
    dis_kernel<<<cdiv(NN, TB), TB>>>(p_rowptr, p_dis);

    for (int layer = 0; layer < 2; layer++) {
        const float* a_s = layer ? a2s : a1s;
        const float* a_d = layer ? a2d : a1d;
        const float* bb  = layer ? b2  : b1;
        float* outbuf    = layer ? p_h2f : p_h1f;

        if (layer == 0) gemm_kernel<64><<<ggrid, TB>>>(x, W1, p_h, NN);
        else            gemm_kernel<256><<<ggrid, TB>>>(p_h1f, W2, p_h, NN);

        attn_scores_kernel<<<cdiv((long)NN * NH, TB), TB>>>(p_h, a_s, a_d, p_es, p_ed);
        softmax_kernel<<<cdiv((long)NN * NH, TB), TB>>>(p_rowptr, p_srcs, p_es, p_ed, p_alpha);
        gat_gather_kernel<<<cdiv((long)NN * 64, TB), TB>>>(p_rowptr, p_srcs, p_h, p_alpha, bb, p_pre);

        lp_gather_kernel<<<cdiv((long)NN * 64, TB), TB>>>(p_rowptr, p_srcs, p_pre, p_dis, p_pre, p_acc);
        lp_gather_kernel<<<cdiv((long)NN * 64, TB), TB>>>(p_rowptr, p_srcs, p_acc, p_dis, p_pre, outbuf);
    }

    // ================= pooling + heads =================
    pool_kernel<<<NG, JK>>>(x, p_h1f, p_h2f, batch, p_gmean);
    head_kernel<<<NG, TB>>>(p_gmean, clin,
                            pp_w1, pp_b1, pp_w2, pp_b2,
                            cl_w1, cl_b1, cl_w2, cl_b2,
                            h_w1, h_b1, h_w2, h_b2, h_w3, h_b3,
                            out);
}

// round 6
// speedup vs baseline: 3.6015x; 1.0489x over previous
#include <cuda_runtime.h>

#define NN 50000
#define NE 800000
#define NG 128
#define NH 4
#define HD 64
#define HC 256      // NH*HD
#define JK 576      // 64 + 256 + 256

// ---------------- scratch (static device globals; no allocation) ----------
__device__ float g_h   [NN*HC];   // GEMM output (per-head features)
__device__ float g_acc [NN*HC];   // LP ping buffer
__device__ float g_pre [NN*HC];   // relu(gat)+bias  (LP base/residual)
__device__ float g_h1f [NN*HC];   // h1 after label-prop
__device__ float g_h2f [NN*HC];   // h2 after label-prop
__device__ float g_es  [NN*NH];
__device__ float g_ed  [NN*NH];
__device__ float g_alpha[NE*NH];  // CSR-position-ordered attention weights
__device__ float g_dis [NN];
__device__ int   g_cnt [NN];
__device__ int   g_pos [NN];
__device__ int   g_rowptr[NN+1];
__device__ int   g_srcs[NE];      // CSR-ordered source node ids
__device__ float g_gmean[NG*JK];

// ---------------- CSR construction ----------------------------------------
__global__ void ifill_kernel(int* __restrict__ p, int v, int n) {
    int t = blockIdx.x * blockDim.x + threadIdx.x;
    for (; t < n; t += gridDim.x * blockDim.x) p[t] = v;
}

__global__ void count_deg_kernel(const int* __restrict__ dst, int* __restrict__ cnt) {
    int e = blockIdx.x * blockDim.x + threadIdx.x;
    if (e >= NE) return;
    atomicAdd(&cnt[dst[e]], 1);
}

__global__ void scan_kernel(const int* __restrict__ cnt, int* __restrict__ rowptr,
                            int* __restrict__ pos) {
    __shared__ int part[1024];
    int tid = threadIdx.x;
    const int CH = (NN + 1023) / 1024;
    int start = tid * CH;
    int end = start + CH < NN ? start + CH : NN;
    int s = 0;
    for (int i = start; i < end; i++) s += cnt[i];
    part[tid] = s;
    __syncthreads();
    for (int off = 1; off < 1024; off <<= 1) {
        int u = (tid >= off) ? part[tid - off] : 0;
        __syncthreads();
        part[tid] += u;
        __syncthreads();
    }
    int base = (tid > 0) ? part[tid - 1] : 0;
    for (int i = start; i < end; i++) {
        rowptr[i] = base;
        pos[i] = base;
        base += cnt[i];
    }
    if (tid == 1023) rowptr[NN] = part[1023];
}

// Write CSR-ordered source ids directly (no eperm indirection downstream).
__global__ void perm_kernel(const int* __restrict__ src, const int* __restrict__ dst,
                            int* __restrict__ pos, int* __restrict__ srcs) {
    int e = blockIdx.x * blockDim.x + threadIdx.x;
    if (e >= NE) return;
    int p = atomicAdd(&pos[dst[e]], 1);
    srcs[p] = src[e];
}

__global__ void dis_kernel(const int* __restrict__ rowptr, float* __restrict__ dis) {
    int t = blockIdx.x * blockDim.x + threadIdx.x;
    if (t >= NN) return;
    int dg = rowptr[t + 1] - rowptr[t];
    dis[t] = (dg > 0) ? rsqrtf((float)dg) : 0.0f;
}

// ---------------- GEMM: C[nrows,256] = A[nrows,K] @ W[K,256] --------------
// 128x64 block tile, 8x4 per thread (256 threads).
template <int K>
__global__ void __launch_bounds__(256)
gemm_kernel(const float* __restrict__ A,
            const float* __restrict__ W,
            float* __restrict__ C, int nrows) {
    __shared__ float As[16][128];
    __shared__ float Bs[16][64];
    const int col0 = blockIdx.x * 64;
    const int row0 = blockIdx.y * 128;
    const int tx = threadIdx.x % 16;   // col group (4 cols)
    const int ty = threadIdx.x / 16;   // row group (8 rows)
    float acc[8][4] = {};

    for (int k0 = 0; k0 < K; k0 += 16) {
        #pragma unroll
        for (int i = threadIdx.x; i < 128 * 16; i += 256) {
            int r = i >> 4, kk = i & 15;
            int gr = row0 + r;
            As[kk][r] = (gr < nrows) ? A[(long)gr * K + k0 + kk] : 0.0f;
        }
        #pragma unroll
        for (int i = threadIdx.x; i < 16 * 64; i += 256) {
            int kk = i >> 6, c = i & 63;
            Bs[kk][c] = W[(k0 + kk) * 256 + col0 + c];
        }
        __syncthreads();
        #pragma unroll
        for (int kk = 0; kk < 16; kk++) {
            float a[8], b[4];
            #pragma unroll
            for (int i = 0; i < 8; i++) a[i] = As[kk][ty * 8 + i];
            #pragma unroll
            for (int j = 0; j < 4; j++) b[j] = Bs[kk][tx * 4 + j];
            #pragma unroll
            for (int i = 0; i < 8; i++)
                #pragma unroll
                for (int j = 0; j < 4; j++) acc[i][j] += a[i] * b[j];
        }
        __syncthreads();
    }
    #pragma unroll
    for (int i = 0; i < 8; i++) {
        int gr = row0 + ty * 8 + i;
        if (gr < nrows) {
            float4 v = make_float4(acc[i][0], acc[i][1], acc[i][2], acc[i][3]);
            *(float4*)&C[(long)gr * 256 + col0 + tx * 4] = v;
        }
    }
}

// ---------------- GAT attention ------------------------------------------
__global__ void attn_scores_kernel(const float* __restrict__ h,
                                   const float* __restrict__ a_s,
                                   const float* __restrict__ a_d,
                                   float* __restrict__ es, float* __restrict__ ed) {
    int t = blockIdx.x * blockDim.x + threadIdx.x;
    if (t >= NN * NH) return;
    int nod = t >> 2, hd = t & 3;
    const float* hp = h + (long)nod * HC + hd * HD;
    const float* ap = a_s + hd * HD;
    const float* bp = a_d + hd * HD;
    float s = 0.f, d = 0.f;
    #pragma unroll
    for (int c = 0; c < HD; c++) { float v = hp[c]; s += v * ap[c]; d += v * bp[c]; }
    es[t] = s; ed[t] = d;
}

__device__ __forceinline__ float4 lrelu4(float4 v) {
    v.x = (v.x >= 0.f) ? v.x : 0.2f * v.x;
    v.y = (v.y >= 0.f) ? v.y : 0.2f * v.y;
    v.z = (v.z >= 0.f) ? v.z : 0.2f * v.z;
    v.w = (v.w >= 0.f) ? v.w : 0.2f * v.w;
    return v;
}

// Per-node softmax over incoming edges, all 4 heads at once (float4).
__global__ void softmax_kernel(const int* __restrict__ rowptr, const int* __restrict__ srcs,
                               const float* __restrict__ es, const float* __restrict__ ed,
                               float* __restrict__ alpha) {
    int n = blockIdx.x * blockDim.x + threadIdx.x;
    if (n >= NN) return;
    int b = rowptr[n], e_ = rowptr[n + 1];
    float4 edn = ((const float4*)ed)[n];
    float4 m = make_float4(-1e30f, -1e30f, -1e30f, -1e30f);
    for (int i = b; i < e_; i++) {
        float4 v = ((const float4*)es)[srcs[i]];
        v.x += edn.x; v.y += edn.y; v.z += edn.z; v.w += edn.w;
        v = lrelu4(v);
        m.x = fmaxf(m.x, v.x); m.y = fmaxf(m.y, v.y);
        m.z = fmaxf(m.z, v.z); m.w = fmaxf(m.w, v.w);
    }
    float4 den = make_float4(0.f, 0.f, 0.f, 0.f);
    for (int i = b; i < e_; i++) {
        float4 v = ((const float4*)es)[srcs[i]];
        v.x += edn.x; v.y += edn.y; v.z += edn.z; v.w += edn.w;
        v = lrelu4(v);
        float4 ex;
        ex.x = __expf(v.x - m.x); ex.y = __expf(v.y - m.y);
        ex.z = __expf(v.z - m.z); ex.w = __expf(v.w - m.w);
        ((float4*)alpha)[i] = ex;
        den.x += ex.x; den.y += ex.y; den.z += ex.z; den.w += ex.w;
    }
    float4 inv;
    inv.x = (den.x > 0.f) ? 1.0f / den.x : 1.0f;
    inv.y = (den.y > 0.f) ? 1.0f / den.y : 1.0f;
    inv.z = (den.z > 0.f) ? 1.0f / den.z : 1.0f;
    inv.w = (den.w > 0.f) ? 1.0f / den.w : 1.0f;
    for (int i = b; i < e_; i++) {
        float4 a = ((float4*)alpha)[i];
        a.x *= inv.x; a.y *= inv.y; a.z *= inv.z; a.w *= inv.w;
        ((float4*)alpha)[i] = a;
    }
}

// Gather-aggregate + bias + relu fused. One thread per (node, float4 lane).
__global__ void gat_gather_kernel(const int* __restrict__ rowptr, const int* __restrict__ srcs,
                                  const float* __restrict__ h, const float* __restrict__ alpha,
                                  const float* __restrict__ bias, float* __restrict__ out) {
    int t = blockIdx.x * blockDim.x + threadIdx.x;
    if (t >= NN * 64) return;
    int n = t >> 6, j = t & 63;
    int hd = j >> 4;
    int b = rowptr[n], e_ = rowptr[n + 1];
    float4 acc = make_float4(0.f, 0.f, 0.f, 0.f);
    for (int i = b; i < e_; i++) {
        int s = srcs[i];
        float a = alpha[i * NH + hd];
        float4 v = *(const float4*)&h[(long)s * HC + j * 4];
        acc.x += a * v.x; acc.y += a * v.y; acc.z += a * v.z; acc.w += a * v.w;
    }
    float4 bb = ((const float4*)bias)[j];
    acc.x = fmaxf(acc.x + bb.x, 0.f);
    acc.y = fmaxf(acc.y + bb.y, 0.f);
    acc.z = fmaxf(acc.z + bb.z, 0.f);
    acc.w = fmaxf(acc.w + bb.w, 0.f);
    ((float4*)out)[t] = acc;
}

// LP gather + mix + clamp fused. out = clamp(0.5*gather(in) + 0.5*base, 0, 1)
__global__ void lp_gather_kernel(const int* __restrict__ rowptr, const int* __restrict__ srcs,
                                 const float* __restrict__ in, const float* __restrict__ dis,
                                 const float* __restrict__ base, float* __restrict__ out) {
    int t = blockIdx.x * blockDim.x + threadIdx.x;
    if (t >= NN * 64) return;
    int n = t >> 6, j = t & 63;
    int b = rowptr[n], e_ = rowptr[n + 1];
    float dn = dis[n];
    float4 acc = make_float4(0.f, 0.f, 0.f, 0.f);
    for (int i = b; i < e_; i++) {
        int s = srcs[i];
        float w = dis[s];
        float4 v = *(const float4*)&in[(long)s * HC + j * 4];
        acc.x += w * v.x; acc.y += w * v.y; acc.z += w * v.z; acc.w += w * v.w;
    }
    float4 bs = ((const float4*)base)[t];
    float4 o;
    o.x = fminf(fmaxf(0.5f * dn * acc.x + 0.5f * bs.x, 0.f), 1.f);
    o.y = fminf(fmaxf(0.5f * dn * acc.y + 0.5f * bs.y, 0.f), 1.f);
    o.z = fminf(fmaxf(0.5f * dn * acc.z + 0.5f * bs.z, 0.f), 1.f);
    o.w = fminf(fmaxf(0.5f * dn * acc.w + 0.5f * bs.w, 0.f), 1.f);
    ((float4*)out)[t] = o;
}

// ---------------- Pooling (batch is sorted -> contiguous ranges) ----------
__device__ __forceinline__ int lower_bound_batch(const int* __restrict__ batch, int key) {
    int lo = 0, hi = NN;
    while (lo < hi) {
        int mid = (lo + hi) >> 1;
        if (batch[mid] < key) lo = mid + 1; else hi = mid;
    }
    return lo;
}

__global__ void pool_kernel(const float* __restrict__ x,
                            const float* __restrict__ h1, const float* __restrict__ h2,
                            const int* __restrict__ batch, float* __restrict__ gmean) {
    int b = blockIdx.x;          // graph id
    int tid = threadIdx.x;       // 0..575 = column
    __shared__ int s_start, s_end;
    if (tid == 0) {
        s_start = lower_bound_batch(batch, b);
        s_end   = lower_bound_batch(batch, b + 1);
    }
    __syncthreads();
    int start = s_start, end = s_end;
    float s = 0.f;
    if (tid < 64) {
        for (int n = start; n < end; n++) s += x[(long)n * 64 + tid];
    } else if (tid < 320) {
        int c = tid - 64;
        for (int n = start; n < end; n++) s += h1[(long)n * HC + c];
    } else {
        int c = tid - 320;
        for (int n = start; n < end; n++) s += h2[(long)n * HC + c];
    }
    float cnt = (float)(end - start);
    cnt = fmaxf(cnt, 1.0f);
    gmean[b * JK + tid] = s / cnt;
}

// ---------------- Head MLPs (one block per graph) -------------------------
__global__ void head_kernel(const float* __restrict__ gmean,
                            const float* __restrict__ clin,
                            const float* __restrict__ pp_w1, const float* __restrict__ pp_b1,
                            const float* __restrict__ pp_w2, const float* __restrict__ pp_b2,
                            const float* __restrict__ cl_w1, const float* __restrict__ cl_b1,
                            const float* __restrict__ cl_w2, const float* __restrict__ cl_b2,
                            const float* __restrict__ h_w1, const float* __restrict__ h_b1,
                            const float* __restrict__ h_w2, const float* __restrict__ h_b2,
                            const float* __restrict__ h_w3, const float* __restrict__ h_b3,
                            float* __restrict__ out) {
    __shared__ float g[JK];
    __shared__ float t1[256];
    __shared__ float z[160];
    __shared__ float c1s[64];
    __shared__ float t3[64];
    __shared__ float t4[32];
    int b = blockIdx.x, tid = threadIdx.x;
    for (int i = tid; i < JK; i += 256) g[i] = gmean[b * JK + i];
    __syncthreads();

    // pp layer1: 576 -> 256 (relu)
    {
        float o = pp_b1[tid];
        for (int k = 0; k < JK; k++) o += g[k] * pp_w1[k * 256 + tid];
        t1[tid] = o > 0.f ? o : 0.f;
    }
    __syncthreads();
    // pp layer2: 256 -> 128
    if (tid < 128) {
        float o = pp_b2[tid];
        for (int k = 0; k < 256; k++) o += t1[k] * pp_w2[k * 128 + tid];
        z[tid] = o;
    }
    // clinical layer1: 32 -> 64 (relu)
    if (tid >= 128 && tid < 192) {
        int c = tid - 128;
        float o = cl_b1[c];
        for (int k = 0; k < 32; k++) o += clin[b * 32 + k] * cl_w1[k * 64 + c];
        c1s[c] = o > 0.f ? o : 0.f;
    }
    __syncthreads();
    // clinical layer2: 64 -> 32
    if (tid < 32) {
        float o = cl_b2[tid];
        for (int k = 0; k < 64; k++) o += c1s[k] * cl_w2[k * 32 + tid];
        z[128 + tid] = o;
    }
    __syncthreads();
    // head 1: 160 -> 64 (relu)
    if (tid < 64) {
        float o = h_b1[tid];
        for (int k = 0; k < 160; k++) o += z[k] * h_w1[k * 64 + tid];
        t3[tid] = o > 0.f ? o : 0.f;
    }
    __syncthreads();
    // head 2: 64 -> 32 (relu)
    if (tid < 32) {
        float o = h_b2[tid];
        for (int k = 0; k < 64; k++) o += t3[k] * h_w2[k * 32 + tid];
        t4[tid] = o > 0.f ? o : 0.f;
    }
    __syncthreads();
    // head 3: 32 -> 2
    if (tid < 2) {
        float o = h_b3[tid];
        for (int k = 0; k < 32; k++) o += t4[k] * h_w3[k * 2 + tid];
        out[b * 2 + tid] = o;
    }
}

// ---------------- launch --------------------------------------------------
static inline int cdiv(long a, int b) { return (int)((a + b - 1) / b); }

extern "C" void kernel_launch(void* const* d_in, const int* in_sizes, int n_in,
                              void* d_out, int out_size) {
    const float* x     = (const float*)d_in[0];
    const int*   ei    = (const int*)  d_in[1];
    const int*   batch = (const int*)  d_in[2];
    const float* clin  = (const float*)d_in[3];
    const float* W1  = (const float*)d_in[4];
    const float* a1s = (const float*)d_in[5];
    const float* a1d = (const float*)d_in[6];
    const float* b1  = (const float*)d_in[7];
    const float* W2  = (const float*)d_in[8];
    const float* a2s = (const float*)d_in[9];
    const float* a2d = (const float*)d_in[10];
    const float* b2  = (const float*)d_in[11];
    const float* pp_w1 = (const float*)d_in[12];
    const float* pp_b1 = (const float*)d_in[13];
    const float* pp_w2 = (const float*)d_in[14];
    const float* pp_b2 = (const float*)d_in[15];
    const float* cl_w1 = (const float*)d_in[16];
    const float* cl_b1 = (const float*)d_in[17];
    const float* cl_w2 = (const float*)d_in[18];
    const float* cl_b2 = (const float*)d_in[19];
    const float* h_w1 = (const float*)d_in[20];
    const float* h_b1 = (const float*)d_in[21];
    const float* h_w2 = (const float*)d_in[22];
    const float* h_b2 = (const float*)d_in[23];
    const float* h_w3 = (const float*)d_in[24];
    const float* h_b3 = (const float*)d_in[25];
    float* out = (float*)d_out;

    const int* src = ei;
    const int* dst = ei + NE;

    float *p_h, *p_acc, *p_pre, *p_h1f, *p_h2f, *p_es, *p_ed, *p_alpha, *p_dis, *p_gmean;
    int *p_cnt, *p_pos, *p_rowptr, *p_srcs;
    cudaGetSymbolAddress((void**)&p_h,     g_h);
    cudaGetSymbolAddress((void**)&p_acc,   g_acc);
    cudaGetSymbolAddress((void**)&p_pre,   g_pre);
    cudaGetSymbolAddress((void**)&p_h1f,   g_h1f);
    cudaGetSymbolAddress((void**)&p_h2f,   g_h2f);
    cudaGetSymbolAddress((void**)&p_es,    g_es);
    cudaGetSymbolAddress((void**)&p_ed,    g_ed);
    cudaGetSymbolAddress((void**)&p_alpha, g_alpha);
    cudaGetSymbolAddress((void**)&p_dis,   g_dis);
    cudaGetSymbolAddress((void**)&p_gmean, g_gmean);
    cudaGetSymbolAddress((void**)&p_cnt,   g_cnt);
    cudaGetSymbolAddress((void**)&p_pos,   g_pos);
    cudaGetSymbolAddress((void**)&p_rowptr,g_rowptr);
    cudaGetSymbolAddress((void**)&p_srcs,  g_srcs);

    const int TB = 256;
    dim3 ggrid(4, cdiv(NN, 128));

    // ---- CSR by dst (shared by softmax, GAT gather, LP gather) ----
    ifill_kernel<<<64, TB>>>(p_cnt, 0, NN);
    count_deg_kernel<<<cdiv(NE, TB), TB>>>(dst, p_cnt);
    scan_kernel<<<1, 1024>>>(p_cnt, p_rowptr, p_pos);
    perm_kernel<<<cdiv(NE, TB), TB>>>(src, dst, p_pos, p_srcs);
    dis_kernel<<<cdiv(NN, TB), TB>>>(p_rowptr, p_dis);

    for (int layer = 0; layer < 2; layer++) {
        const float* a_s = layer ? a2s : a1s;
        const float* a_d = layer ? a2d : a1d;
        const float* bb  = layer ? b2  : b1;
        float* outbuf    = layer ? p_h2f : p_h1f;

        if (layer == 0) gemm_kernel<64><<<ggrid, TB>>>(x, W1, p_h, NN);
        else            gemm_kernel<256><<<ggrid, TB>>>(p_h1f, W2, p_h, NN);

        attn_scores_kernel<<<cdiv((long)NN * NH, TB), TB>>>(p_h, a_s, a_d, p_es, p_ed);
        softmax_kernel<<<cdiv(NN, TB), TB>>>(p_rowptr, p_srcs, p_es, p_ed, p_alpha);
        gat_gather_kernel<<<cdiv((long)NN * 64, TB), TB>>>(p_rowptr, p_srcs, p_h, p_alpha, bb, p_pre);

        lp_gather_kernel<<<cdiv((long)NN * 64, TB), TB>>>(p_rowptr, p_srcs, p_pre, p_dis, p_pre, p_acc);
        lp_gather_kernel<<<cdiv((long)NN * 64, TB), TB>>>(p_rowptr, p_srcs, p_acc, p_dis, p_pre, outbuf);
    }

    // ================= pooling + heads =================
    pool_kernel<<<NG, JK>>>(x, p_h1f, p_h2f, batch, p_gmean);
    head_kernel<<<NG, TB>>>(p_gmean, clin,
                            pp_w1, pp_b1, pp_w2, pp_b2,
                            cl_w1, cl_b1, cl_w2, cl_b2,
                            h_w1, h_b1, h_w2, h_b2, h_w3, h_b3,
                            out);
}

// round 7
// speedup vs baseline: 3.9381x; 1.0935x over previous
#include <cuda_runtime.h>
#include <cuda_fp16.h>

#define NN 50000
#define NE 800000
#define NG 128
#define NH 4
#define HD 64
#define HC 256      // NH*HD
#define JK 576      // 64 + 256 + 256

// ---------------- scratch (static device globals; no allocation) ----------
__device__ float  g_h   [NN*HC];   // GEMM output (fp32, for attn_scores)
__device__ __half g_hh  [NN*HC];   // fp16 shadow for gather
__device__ float  g_pre [NN*HC];   // relu(gat)+bias (LP base/residual)
__device__ __half g_preh[NN*HC];   // fp16 shadow for gather
__device__ __half g_acch[NN*HC];   // LP intermediate (gather-only -> fp16 only)
__device__ float  g_h1f [NN*HC];   // h1 after label-prop
__device__ float  g_h2f [NN*HC];   // h2 after label-prop
__device__ float  g_es  [NN*NH];
__device__ float  g_ed  [NN*NH];
__device__ float  g_alpha[NE*NH];  // CSR-position-ordered attention weights
__device__ float  g_dis [NN];
__device__ int    g_cnt [NN];
__device__ int    g_pos [NN];
__device__ int    g_rowptr[NN+1];
__device__ int    g_srcs[NE];      // CSR-ordered source node ids
__device__ float  g_gmean[NG*JK];

// ---------------- CSR construction ----------------------------------------
__global__ void ifill_kernel(int* __restrict__ p, int v, int n) {
    int t = blockIdx.x * blockDim.x + threadIdx.x;
    for (; t < n; t += gridDim.x * blockDim.x) p[t] = v;
}

__global__ void count_deg_kernel(const int* __restrict__ dst, int* __restrict__ cnt) {
    int e = blockIdx.x * blockDim.x + threadIdx.x;
    if (e >= NE) return;
    atomicAdd(&cnt[dst[e]], 1);
}

__global__ void scan_kernel(const int* __restrict__ cnt, int* __restrict__ rowptr,
                            int* __restrict__ pos) {
    __shared__ int part[1024];
    int tid = threadIdx.x;
    const int CH = (NN + 1023) / 1024;
    int start = tid * CH;
    int end = start + CH < NN ? start + CH : NN;
    int s = 0;
    for (int i = start; i < end; i++) s += cnt[i];
    part[tid] = s;
    __syncthreads();
    for (int off = 1; off < 1024; off <<= 1) {
        int u = (tid >= off) ? part[tid - off] : 0;
        __syncthreads();
        part[tid] += u;
        __syncthreads();
    }
    int base = (tid > 0) ? part[tid - 1] : 0;
    for (int i = start; i < end; i++) {
        rowptr[i] = base;
        pos[i] = base;
        base += cnt[i];
    }
    if (tid == 1023) rowptr[NN] = part[1023];
}

__global__ void perm_kernel(const int* __restrict__ src, const int* __restrict__ dst,
                            int* __restrict__ pos, int* __restrict__ srcs) {
    int e = blockIdx.x * blockDim.x + threadIdx.x;
    if (e >= NE) return;
    int p = atomicAdd(&pos[dst[e]], 1);
    srcs[p] = src[e];
}

__global__ void dis_kernel(const int* __restrict__ rowptr, float* __restrict__ dis) {
    int t = blockIdx.x * blockDim.x + threadIdx.x;
    if (t >= NN) return;
    int dg = rowptr[t + 1] - rowptr[t];
    dis[t] = (dg > 0) ? rsqrtf((float)dg) : 0.0f;
}

// ---------------- half pack helpers ---------------------------------------
__device__ __forceinline__ uint2 pack_half4(float4 v) {
    __half2 lo = __floats2half2_rn(v.x, v.y);
    __half2 hi = __floats2half2_rn(v.z, v.w);
    uint2 r;
    r.x = *(unsigned*)&lo;
    r.y = *(unsigned*)&hi;
    return r;
}

__device__ __forceinline__ float4 unpack_half4(uint2 r) {
    __half2 lo = *(__half2*)&r.x;
    __half2 hi = *(__half2*)&r.y;
    float2 a = __half22float2(lo);
    float2 b = __half22float2(hi);
    return make_float4(a.x, a.y, b.x, b.y);
}

// ---------------- GEMM: C[nrows,256] = A[nrows,K] @ W[K,256] --------------
// 128x64 block tile, 8x4 per thread (256 threads). Writes fp32 + fp16 shadow.
template <int K>
__global__ void __launch_bounds__(256)
gemm_kernel(const float* __restrict__ A,
            const float* __restrict__ W,
            float* __restrict__ C, __half* __restrict__ Ch, int nrows) {
    __shared__ float As[16][128];
    __shared__ float Bs[16][64];
    const int col0 = blockIdx.x * 64;
    const int row0 = blockIdx.y * 128;
    const int tx = threadIdx.x % 16;
    const int ty = threadIdx.x / 16;
    float acc[8][4] = {};

    for (int k0 = 0; k0 < K; k0 += 16) {
        #pragma unroll
        for (int i = threadIdx.x; i < 128 * 16; i += 256) {
            int r = i >> 4, kk = i & 15;
            int gr = row0 + r;
            As[kk][r] = (gr < nrows) ? A[(long)gr * K + k0 + kk] : 0.0f;
        }
        #pragma unroll
        for (int i = threadIdx.x; i < 16 * 64; i += 256) {
            int kk = i >> 6, c = i & 63;
            Bs[kk][c] = W[(k0 + kk) * 256 + col0 + c];
        }
        __syncthreads();
        #pragma unroll
        for (int kk = 0; kk < 16; kk++) {
            float a[8], b[4];
            #pragma unroll
            for (int i = 0; i < 8; i++) a[i] = As[kk][ty * 8 + i];
            #pragma unroll
            for (int j = 0; j < 4; j++) b[j] = Bs[kk][tx * 4 + j];
            #pragma unroll
            for (int i = 0; i < 8; i++)
                #pragma unroll
                for (int j = 0; j < 4; j++) acc[i][j] += a[i] * b[j];
        }
        __syncthreads();
    }
    #pragma unroll
    for (int i = 0; i < 8; i++) {
        int gr = row0 + ty * 8 + i;
        if (gr < nrows) {
            float4 v = make_float4(acc[i][0], acc[i][1], acc[i][2], acc[i][3]);
            *(float4*)&C[(long)gr * 256 + col0 + tx * 4] = v;
            *(uint2*)&Ch[(long)gr * 256 + col0 + tx * 4] = pack_half4(v);
        }
    }
}

// ---------------- GAT attention ------------------------------------------
__global__ void attn_scores_kernel(const float* __restrict__ h,
                                   const float* __restrict__ a_s,
                                   const float* __restrict__ a_d,
                                   float* __restrict__ es, float* __restrict__ ed) {
    int t = blockIdx.x * blockDim.x + threadIdx.x;
    if (t >= NN * NH) return;
    int nod = t >> 2, hd = t & 3;
    const float* hp = h + (long)nod * HC + hd * HD;
    const float* ap = a_s + hd * HD;
    const float* bp = a_d + hd * HD;
    float s = 0.f, d = 0.f;
    #pragma unroll
    for (int c = 0; c < HD; c++) { float v = hp[c]; s += v * ap[c]; d += v * bp[c]; }
    es[t] = s; ed[t] = d;
}

__device__ __forceinline__ float4 lrelu4(float4 v) {
    v.x = (v.x >= 0.f) ? v.x : 0.2f * v.x;
    v.y = (v.y >= 0.f) ? v.y : 0.2f * v.y;
    v.z = (v.z >= 0.f) ? v.z : 0.2f * v.z;
    v.w = (v.w >= 0.f) ? v.w : 0.2f * v.w;
    return v;
}

// Per-node softmax over incoming edges, all 4 heads at once (float4).
__global__ void softmax_kernel(const int* __restrict__ rowptr, const int* __restrict__ srcs,
                               const float* __restrict__ es, const float* __restrict__ ed,
                               float* __restrict__ alpha) {
    int n = blockIdx.x * blockDim.x + threadIdx.x;
    if (n >= NN) return;
    int b = rowptr[n], e_ = rowptr[n + 1];
    float4 edn = ((const float4*)ed)[n];
    float4 m = make_float4(-1e30f, -1e30f, -1e30f, -1e30f);
    for (int i = b; i < e_; i++) {
        float4 v = ((const float4*)es)[srcs[i]];
        v.x += edn.x; v.y += edn.y; v.z += edn.z; v.w += edn.w;
        v = lrelu4(v);
        m.x = fmaxf(m.x, v.x); m.y = fmaxf(m.y, v.y);
        m.z = fmaxf(m.z, v.z); m.w = fmaxf(m.w, v.w);
    }
    float4 den = make_float4(0.f, 0.f, 0.f, 0.f);
    for (int i = b; i < e_; i++) {
        float4 v = ((const float4*)es)[srcs[i]];
        v.x += edn.x; v.y += edn.y; v.z += edn.z; v.w += edn.w;
        v = lrelu4(v);
        float4 ex;
        ex.x = __expf(v.x - m.x); ex.y = __expf(v.y - m.y);
        ex.z = __expf(v.z - m.z); ex.w = __expf(v.w - m.w);
        ((float4*)alpha)[i] = ex;
        den.x += ex.x; den.y += ex.y; den.z += ex.z; den.w += ex.w;
    }
    float4 inv;
    inv.x = (den.x > 0.f) ? 1.0f / den.x : 1.0f;
    inv.y = (den.y > 0.f) ? 1.0f / den.y : 1.0f;
    inv.z = (den.z > 0.f) ? 1.0f / den.z : 1.0f;
    inv.w = (den.w > 0.f) ? 1.0f / den.w : 1.0f;
    for (int i = b; i < e_; i++) {
        float4 a = ((float4*)alpha)[i];
        a.x *= inv.x; a.y *= inv.y; a.z *= inv.z; a.w *= inv.w;
        ((float4*)alpha)[i] = a;
    }
}

// Gather-aggregate (fp16 rows) + bias + relu fused. Writes fp32 + fp16 shadow.
__global__ void gat_gather_kernel(const int* __restrict__ rowptr, const int* __restrict__ srcs,
                                  const __half* __restrict__ h, const float* __restrict__ alpha,
                                  const float* __restrict__ bias,
                                  float* __restrict__ out, __half* __restrict__ outh) {
    int t = blockIdx.x * blockDim.x + threadIdx.x;
    if (t >= NN * 64) return;
    int n = t >> 6, j = t & 63;
    int hd = j >> 4;
    int b = rowptr[n], e_ = rowptr[n + 1];
    float4 acc = make_float4(0.f, 0.f, 0.f, 0.f);
    for (int i = b; i < e_; i++) {
        int s = srcs[i];
        float a = alpha[i * NH + hd];
        float4 v = unpack_half4(*(const uint2*)&h[(long)s * HC + j * 4]);
        acc.x += a * v.x; acc.y += a * v.y; acc.z += a * v.z; acc.w += a * v.w;
    }
    float4 bb = ((const float4*)bias)[j];
    acc.x = fmaxf(acc.x + bb.x, 0.f);
    acc.y = fmaxf(acc.y + bb.y, 0.f);
    acc.z = fmaxf(acc.z + bb.z, 0.f);
    acc.w = fmaxf(acc.w + bb.w, 0.f);
    ((float4*)out)[t] = acc;
    ((uint2*)outh)[t] = pack_half4(acc);
}

// LP gather (fp16 rows) + mix + clamp. Template picks fp32/fp16 outputs.
template <bool WF, bool WH>
__global__ void lp_gather_kernel(const int* __restrict__ rowptr, const int* __restrict__ srcs,
                                 const __half* __restrict__ in, const float* __restrict__ dis,
                                 const float* __restrict__ base,
                                 float* __restrict__ out, __half* __restrict__ outh) {
    int t = blockIdx.x * blockDim.x + threadIdx.x;
    if (t >= NN * 64) return;
    int n = t >> 6, j = t & 63;
    int b = rowptr[n], e_ = rowptr[n + 1];
    float dn = dis[n];
    float4 acc = make_float4(0.f, 0.f, 0.f, 0.f);
    for (int i = b; i < e_; i++) {
        int s = srcs[i];
        float w = dis[s];
        float4 v = unpack_half4(*(const uint2*)&in[(long)s * HC + j * 4]);
        acc.x += w * v.x; acc.y += w * v.y; acc.z += w * v.z; acc.w += w * v.w;
    }
    float4 bs = ((const float4*)base)[t];
    float4 o;
    o.x = fminf(fmaxf(0.5f * dn * acc.x + 0.5f * bs.x, 0.f), 1.f);
    o.y = fminf(fmaxf(0.5f * dn * acc.y + 0.5f * bs.y, 0.f), 1.f);
    o.z = fminf(fmaxf(0.5f * dn * acc.z + 0.5f * bs.z, 0.f), 1.f);
    o.w = fminf(fmaxf(0.5f * dn * acc.w + 0.5f * bs.w, 0.f), 1.f);
    if (WF) ((float4*)out)[t] = o;
    if (WH) ((uint2*)outh)[t] = pack_half4(o);
}

// ---------------- Pooling (batch is sorted -> contiguous ranges) ----------
__device__ __forceinline__ int lower_bound_batch(const int* __restrict__ batch, int key) {
    int lo = 0, hi = NN;
    while (lo < hi) {
        int mid = (lo + hi) >> 1;
        if (batch[mid] < key) lo = mid + 1; else hi = mid;
    }
    return lo;
}

__global__ void pool_kernel(const float* __restrict__ x,
                            const float* __restrict__ h1, const float* __restrict__ h2,
                            const int* __restrict__ batch, float* __restrict__ gmean) {
    int b = blockIdx.x;
    int tid = threadIdx.x;       // 0..575 = column
    __shared__ int s_start, s_end;
    if (tid == 0) {
        s_start = lower_bound_batch(batch, b);
        s_end   = lower_bound_batch(batch, b + 1);
    }
    __syncthreads();
    int start = s_start, end = s_end;
    float s = 0.f;
    if (tid < 64) {
        for (int n = start; n < end; n++) s += x[(long)n * 64 + tid];
    } else if (tid < 320) {
        int c = tid - 64;
        for (int n = start; n < end; n++) s += h1[(long)n * HC + c];
    } else {
        int c = tid - 320;
        for (int n = start; n < end; n++) s += h2[(long)n * HC + c];
    }
    float cnt = (float)(end - start);
    cnt = fmaxf(cnt, 1.0f);
    gmean[b * JK + tid] = s / cnt;
}

// ---------------- Head MLPs (one block per graph) -------------------------
__global__ void head_kernel(const float* __restrict__ gmean,
                            const float* __restrict__ clin,
                            const float* __restrict__ pp_w1, const float* __restrict__ pp_b1,
                            const float* __restrict__ pp_w2, const float* __restrict__ pp_b2,
                            const float* __restrict__ cl_w1, const float* __restrict__ cl_b1,
                            const float* __restrict__ cl_w2, const float* __restrict__ cl_b2,
                            const float* __restrict__ h_w1, const float* __restrict__ h_b1,
                            const float* __restrict__ h_w2, const float* __restrict__ h_b2,
                            const float* __restrict__ h_w3, const float* __restrict__ h_b3,
                            float* __restrict__ out) {
    __shared__ float g[JK];
    __shared__ float t1[256];
    __shared__ float z[160];
    __shared__ float c1s[64];
    __shared__ float t3[64];
    __shared__ float t4[32];
    int b = blockIdx.x, tid = threadIdx.x;
    for (int i = tid; i < JK; i += 256) g[i] = gmean[b * JK + i];
    __syncthreads();

    {
        float o = pp_b1[tid];
        for (int k = 0; k < JK; k++) o += g[k] * pp_w1[k * 256 + tid];
        t1[tid] = o > 0.f ? o : 0.f;
    }
    __syncthreads();
    if (tid < 128) {
        float o = pp_b2[tid];
        for (int k = 0; k < 256; k++) o += t1[k] * pp_w2[k * 128 + tid];
        z[tid] = o;
    }
    if (tid >= 128 && tid < 192) {
        int c = tid - 128;
        float o = cl_b1[c];
        for (int k = 0; k < 32; k++) o += clin[b * 32 + k] * cl_w1[k * 64 + c];
        c1s[c] = o > 0.f ? o : 0.f;
    }
    __syncthreads();
    if (tid < 32) {
        float o = cl_b2[tid];
        for (int k = 0; k < 64; k++) o += c1s[k] * cl_w2[k * 32 + tid];
        z[128 + tid] = o;
    }
    __syncthreads();
    if (tid < 64) {
        float o = h_b1[tid];
        for (int k = 0; k < 160; k++) o += z[k] * h_w1[k * 64 + tid];
        t3[tid] = o > 0.f ? o : 0.f;
    }
    __syncthreads();
    if (tid < 32) {
        float o = h_b2[tid];
        for (int k = 0; k < 64; k++) o += t3[k] * h_w2[k * 32 + tid];
        t4[tid] = o > 0.f ? o : 0.f;
    }
    __syncthreads();
    if (tid < 2) {
        float o = h_b3[tid];
        for (int k = 0; k < 32; k++) o += t4[k] * h_w3[k * 2 + tid];
        out[b * 2 + tid] = o;
    }
}

// ---------------- launch --------------------------------------------------
static inline int cdiv(long a, int b) { return (int)((a + b - 1) / b); }

extern "C" void kernel_launch(void* const* d_in, const int* in_sizes, int n_in,
                              void* d_out, int out_size) {
    const float* x     = (const float*)d_in[0];
    const int*   ei    = (const int*)  d_in[1];
    const int*   batch = (const int*)  d_in[2];
    const float* clin  = (const float*)d_in[3];
    const float* W1  = (const float*)d_in[4];
    const float* a1s = (const float*)d_in[5];
    const float* a1d = (const float*)d_in[6];
    const float* b1  = (const float*)d_in[7];
    const float* W2  = (const float*)d_in[8];
    const float* a2s = (const float*)d_in[9];
    const float* a2d = (const float*)d_in[10];
    const float* b2  = (const float*)d_in[11];
    const float* pp_w1 = (const float*)d_in[12];
    const float* pp_b1 = (const float*)d_in[13];
    const float* pp_w2 = (const float*)d_in[14];
    const float* pp_b2 = (const float*)d_in[15];
    const float* cl_w1 = (const float*)d_in[16];
    const float* cl_b1 = (const float*)d_in[17];
    const float* cl_w2 = (const float*)d_in[18];
    const float* cl_b2 = (const float*)d_in[19];
    const float* h_w1 = (const float*)d_in[20];
    const float* h_b1 = (const float*)d_in[21];
    const float* h_w2 = (const float*)d_in[22];
    const float* h_b2 = (const float*)d_in[23];
    const float* h_w3 = (const float*)d_in[24];
    const float* h_b3 = (const float*)d_in[25];
    float* out = (float*)d_out;

    const int* src = ei;
    const int* dst = ei + NE;

    float *p_h, *p_pre, *p_h1f, *p_h2f, *p_es, *p_ed, *p_alpha, *p_dis, *p_gmean;
    __half *p_hh, *p_preh, *p_acch;
    int *p_cnt, *p_pos, *p_rowptr, *p_srcs;
    cudaGetSymbolAddress((void**)&p_h,     g_h);
    cudaGetSymbolAddress((void**)&p_hh,    g_hh);
    cudaGetSymbolAddress((void**)&p_pre,   g_pre);
    cudaGetSymbolAddress((void**)&p_preh,  g_preh);
    cudaGetSymbolAddress((void**)&p_acch,  g_acch);
    cudaGetSymbolAddress((void**)&p_h1f,   g_h1f);
    cudaGetSymbolAddress((void**)&p_h2f,   g_h2f);
    cudaGetSymbolAddress((void**)&p_es,    g_es);
    cudaGetSymbolAddress((void**)&p_ed,    g_ed);
    cudaGetSymbolAddress((void**)&p_alpha, g_alpha);
    cudaGetSymbolAddress((void**)&p_dis,   g_dis);
    cudaGetSymbolAddress((void**)&p_gmean, g_gmean);
    cudaGetSymbolAddress((void**)&p_cnt,   g_cnt);
    cudaGetSymbolAddress((void**)&p_pos,   g_pos);
    cudaGetSymbolAddress((void**)&p_rowptr,g_rowptr);
    cudaGetSymbolAddress((void**)&p_srcs,  g_srcs);

    const int TB = 256;
    dim3 ggrid(4, cdiv(NN, 128));

    // ---- CSR by dst (shared by softmax, GAT gather, LP gather) ----
    ifill_kernel<<<64, TB>>>(p_cnt, 0, NN);
    count_deg_kernel<<<cdiv(NE, TB), TB>>>(dst, p_cnt);
    scan_kernel<<<1, 1024>>>(p_cnt, p_rowptr, p_pos);
    perm_kernel<<<cdiv(NE, TB), TB>>>(src, dst, p_pos, p_srcs);
    dis_kernel<<<cdiv(NN, TB), TB>>>(p_rowptr, p_dis);

    for (int layer = 0; layer < 2; layer++) {
        const float* a_s = layer ? a2s : a1s;
        const float* a_d = layer ? a2d : a1d;
        const float* bb  = layer ? b2  : b1;
        float* outbuf    = layer ? p_h2f : p_h1f;

        if (layer == 0) gemm_kernel<64><<<ggrid, TB>>>(x, W1, p_h, p_hh, NN);
        else            gemm_kernel<256><<<ggrid, TB>>>(p_h1f, W2, p_h, p_hh, NN);

        attn_scores_kernel<<<cdiv((long)NN * NH, TB), TB>>>(p_h, a_s, a_d, p_es, p_ed);
        softmax_kernel<<<cdiv(NN, TB), TB>>>(p_rowptr, p_srcs, p_es, p_ed, p_alpha);
        gat_gather_kernel<<<cdiv((long)NN * 64, TB), TB>>>(p_rowptr, p_srcs, p_hh, p_alpha, bb, p_pre, p_preh);

        // LP iter 1: in=preh, base=pre -> acch (fp16 only)
        lp_gather_kernel<false, true><<<cdiv((long)NN * 64, TB), TB>>>(
            p_rowptr, p_srcs, p_preh, p_dis, p_pre, nullptr, p_acch);
        // LP iter 2: in=acch, base=pre -> outbuf (fp32 only)
        lp_gather_kernel<true, false><<<cdiv((long)NN * 64, TB), TB>>>(
            p_rowptr, p_srcs, p_acch, p_dis, p_pre, outbuf, nullptr);
    }

    // ================= pooling + heads =================
    pool_kernel<<<NG, JK>>>(x, p_h1f, p_h2f, batch, p_gmean);
    head_kernel<<<NG, TB>>>(p_gmean, clin,
                            pp_w1, pp_b1, pp_w2, pp_b2,
                            cl_w1, cl_b1, cl_w2, cl_b2,
                            h_w1, h_b1, h_w2, h_b2, h_w3, h_b3,
                            out);
}